// round 1
// baseline (speedup 1.0000x reference)
#include <cuda_runtime.h>
#include <math.h>

// ---------------------------------------------------------------------------
// SingleHeadAttention  B=4, T=2048, C=1024  (fp32)
//   qkv = x @ w^T            [8192, 3072]
//   S   = q k^T / sqrt(C)    per batch [2048, 2048], causal
//   P   = softmax(S) (in-place, zeros above diagonal)
//   y   = P v                [8192, 1024]
// Round 0 baseline: register-blocked fp32 SGEMM (128x128x8, 8x8/thread).
// ---------------------------------------------------------------------------

#define BM 128
#define BN 128
#define BK 8

// scratch (static device arrays: allocation-free rule)
__device__ float g_qkv[(size_t)8192 * 3072];          // ~100.7 MB
__device__ float g_att[(size_t)4 * 2048 * 2048];      // ~67 MB

// ---------------------------------------------------------------------------
// C[m,n] = alpha * sum_k A[m,k] * B[n,k]     (NT: both K-major)
// causal=1: skip tiles with n0 > m0+BM-1 (fully masked)
// ---------------------------------------------------------------------------
__global__ __launch_bounds__(256, 2)
void gemm_nt_kernel(const float* __restrict__ A, const float* __restrict__ B,
                    float* __restrict__ C,
                    int M, int N, int K, int lda, int ldb, int ldc,
                    long long sA, long long sB, long long sC,
                    float alpha, int causal)
{
    const int bz = blockIdx.z;
    A += (long long)bz * sA;
    B += (long long)bz * sB;
    C += (long long)bz * sC;

    const int m0 = blockIdx.y * BM;
    const int n0 = blockIdx.x * BN;
    if (causal && n0 > m0 + (BM - 1)) return;   // fully above diagonal

    __shared__ float As[BK][BM];
    __shared__ float Bs[BK][BN];

    const int tid = threadIdx.x;
    const int tx  = tid & 15;        // 0..15  -> n micro-tile
    const int ty  = tid >> 4;        // 0..15  -> m micro-tile

    const int lrow = tid >> 1;       // 0..127
    const int lk   = (tid & 1) * 4;  // 0 or 4

    float acc[8][8];
#pragma unroll
    for (int i = 0; i < 8; i++)
#pragma unroll
        for (int j = 0; j < 8; j++) acc[i][j] = 0.f;

    for (int k0 = 0; k0 < K; k0 += BK) {
        float4 av = *(const float4*)(A + (long long)(m0 + lrow) * lda + k0 + lk);
        float4 bv = *(const float4*)(B + (long long)(n0 + lrow) * ldb + k0 + lk);
        As[lk + 0][lrow] = av.x; As[lk + 1][lrow] = av.y;
        As[lk + 2][lrow] = av.z; As[lk + 3][lrow] = av.w;
        Bs[lk + 0][lrow] = bv.x; Bs[lk + 1][lrow] = bv.y;
        Bs[lk + 2][lrow] = bv.z; Bs[lk + 3][lrow] = bv.w;
        __syncthreads();

#pragma unroll
        for (int k = 0; k < BK; k++) {
            float4 a0 = *(const float4*)&As[k][ty * 8];
            float4 a1 = *(const float4*)&As[k][ty * 8 + 4];
            float4 b0 = *(const float4*)&Bs[k][tx * 8];
            float4 b1 = *(const float4*)&Bs[k][tx * 8 + 4];
            float a[8] = {a0.x, a0.y, a0.z, a0.w, a1.x, a1.y, a1.z, a1.w};
            float b[8] = {b0.x, b0.y, b0.z, b0.w, b1.x, b1.y, b1.z, b1.w};
#pragma unroll
            for (int i = 0; i < 8; i++)
#pragma unroll
                for (int j = 0; j < 8; j++)
                    acc[i][j] = fmaf(a[i], b[j], acc[i][j]);
        }
        __syncthreads();
    }

#pragma unroll
    for (int i = 0; i < 8; i++) {
        const int row = m0 + ty * 8 + i;
        float4 o0, o1;
        o0.x = alpha * acc[i][0]; o0.y = alpha * acc[i][1];
        o0.z = alpha * acc[i][2]; o0.w = alpha * acc[i][3];
        o1.x = alpha * acc[i][4]; o1.y = alpha * acc[i][5];
        o1.z = alpha * acc[i][6]; o1.w = alpha * acc[i][7];
        *(float4*)(C + (long long)row * ldc + n0 + tx * 8)     = o0;
        *(float4*)(C + (long long)row * ldc + n0 + tx * 8 + 4) = o1;
    }
}

// ---------------------------------------------------------------------------
// C[m,n] = alpha * sum_k A[m,k] * B[k,n]     (NN: A K-major, B N-major)
// causal=1: limit K to m0+BM (rows above rely on zeros written by softmax)
// ---------------------------------------------------------------------------
__global__ __launch_bounds__(256, 2)
void gemm_nn_kernel(const float* __restrict__ A, const float* __restrict__ B,
                    float* __restrict__ C,
                    int M, int N, int K, int lda, int ldb, int ldc,
                    long long sA, long long sB, long long sC,
                    float alpha, int causal)
{
    const int bz = blockIdx.z;
    A += (long long)bz * sA;
    B += (long long)bz * sB;
    C += (long long)bz * sC;

    const int m0 = blockIdx.y * BM;
    const int n0 = blockIdx.x * BN;

    int Keff = K;
    if (causal) { int lim = m0 + BM; Keff = (lim < K) ? lim : K; }

    __shared__ float As[BK][BM];
    __shared__ float Bs[BK][BN];

    const int tid = threadIdx.x;
    const int tx  = tid & 15;
    const int ty  = tid >> 4;

    const int lrow = tid >> 1;        // A: 0..127
    const int lk   = (tid & 1) * 4;   // A: 0 or 4
    const int lkb  = tid >> 5;        // B: k row 0..7
    const int lnb  = (tid & 31) * 4;  // B: n col 0..124

    float acc[8][8];
#pragma unroll
    for (int i = 0; i < 8; i++)
#pragma unroll
        for (int j = 0; j < 8; j++) acc[i][j] = 0.f;

    for (int k0 = 0; k0 < Keff; k0 += BK) {
        float4 av = *(const float4*)(A + (long long)(m0 + lrow) * lda + k0 + lk);
        As[lk + 0][lrow] = av.x; As[lk + 1][lrow] = av.y;
        As[lk + 2][lrow] = av.z; As[lk + 3][lrow] = av.w;
        float4 bv = *(const float4*)(B + (long long)(k0 + lkb) * ldb + n0 + lnb);
        *(float4*)&Bs[lkb][lnb] = bv;
        __syncthreads();

#pragma unroll
        for (int k = 0; k < BK; k++) {
            float4 a0 = *(const float4*)&As[k][ty * 8];
            float4 a1 = *(const float4*)&As[k][ty * 8 + 4];
            float4 b0 = *(const float4*)&Bs[k][tx * 8];
            float4 b1 = *(const float4*)&Bs[k][tx * 8 + 4];
            float a[8] = {a0.x, a0.y, a0.z, a0.w, a1.x, a1.y, a1.z, a1.w};
            float b[8] = {b0.x, b0.y, b0.z, b0.w, b1.x, b1.y, b1.z, b1.w};
#pragma unroll
            for (int i = 0; i < 8; i++)
#pragma unroll
                for (int j = 0; j < 8; j++)
                    acc[i][j] = fmaf(a[i], b[j], acc[i][j]);
        }
        __syncthreads();
    }

#pragma unroll
    for (int i = 0; i < 8; i++) {
        const int row = m0 + ty * 8 + i;
        float4 o0, o1;
        o0.x = alpha * acc[i][0]; o0.y = alpha * acc[i][1];
        o0.z = alpha * acc[i][2]; o0.w = alpha * acc[i][3];
        o1.x = alpha * acc[i][4]; o1.y = alpha * acc[i][5];
        o1.z = alpha * acc[i][6]; o1.w = alpha * acc[i][7];
        *(float4*)(C + (long long)row * ldc + n0 + tx * 8)     = o0;
        *(float4*)(C + (long long)row * ldc + n0 + tx * 8 + 4) = o1;
    }
}

// ---------------------------------------------------------------------------
// In-place causal softmax over rows of att[b][t][:].  One block per row.
// Writes exact zeros for s > t (required by causal K-limit in PV GEMM).
// ---------------------------------------------------------------------------
__global__ void softmax_causal_kernel(float* __restrict__ att)
{
    const int row = blockIdx.x;              // 0..8191
    const int b = row >> 11;
    const int t = row & 2047;
    float* p = att + (long long)b * 2048 * 2048 + (long long)t * 2048;
    const int n = t + 1;
    const int tid = threadIdx.x;

    __shared__ float sbuf[8];

    // --- row max over [0, n)
    float m = -3.4e38f;
    for (int i = tid; i < n; i += 256) m = fmaxf(m, p[i]);
#pragma unroll
    for (int o = 16; o > 0; o >>= 1) m = fmaxf(m, __shfl_xor_sync(0xffffffffu, m, o));
    if ((tid & 31) == 0) sbuf[tid >> 5] = m;
    __syncthreads();
    if (tid < 8) {
        float v = sbuf[tid];
#pragma unroll
        for (int o = 4; o > 0; o >>= 1) v = fmaxf(v, __shfl_xor_sync(0xffu, v, o));
        if (tid == 0) sbuf[0] = v;
    }
    __syncthreads();
    m = sbuf[0];
    __syncthreads();

    // --- sum of exp
    float s = 0.f;
    for (int i = tid; i < n; i += 256) s += __expf(p[i] - m);
#pragma unroll
    for (int o = 16; o > 0; o >>= 1) s += __shfl_xor_sync(0xffffffffu, s, o);
    if ((tid & 31) == 0) sbuf[tid >> 5] = s;
    __syncthreads();
    if (tid < 8) {
        float v = sbuf[tid];
#pragma unroll
        for (int o = 4; o > 0; o >>= 1) v += __shfl_xor_sync(0xffu, v, o);
        if (tid == 0) sbuf[0] = v;
    }
    __syncthreads();
    const float inv = 1.f / sbuf[0];

    // --- write normalized probs; zeros above diagonal
    for (int i = tid; i < 2048; i += 256)
        p[i] = (i < n) ? __expf(p[i] - m) * inv : 0.f;
}

// ---------------------------------------------------------------------------
extern "C" void kernel_launch(void* const* d_in, const int* in_sizes, int n_in,
                              void* d_out, int out_size)
{
    const float* x = (const float*)d_in[0];     // [4,2048,1024]
    const float* w = (const float*)d_in[1];     // [3072,1024]
    float* out = (float*)d_out;                 // [4,2048,1024]

    float *qkv = nullptr, *att = nullptr;
    cudaGetSymbolAddress((void**)&qkv, g_qkv);
    cudaGetSymbolAddress((void**)&att, g_att);

    const long long sQKV = (long long)2048 * 3072;   // per-batch rows in qkv
    const long long sATT = (long long)2048 * 2048;
    const long long sOUT = (long long)2048 * 1024;

    // 1) qkv = x @ w^T   M=8192 N=3072 K=1024
    {
        dim3 grid(3072 / BN, 8192 / BM, 1);
        gemm_nt_kernel<<<grid, 256>>>(x, w, qkv,
                                      8192, 3072, 1024, 1024, 1024, 3072,
                                      0, 0, 0, 1.0f, 0);
    }
    // 2) S = q k^T / 32  per batch, causal tile skip
    {
        dim3 grid(2048 / BN, 2048 / BM, 4);
        gemm_nt_kernel<<<grid, 256>>>(qkv, qkv + 1024, att,
                                      2048, 2048, 1024, 3072, 3072, 2048,
                                      sQKV, sQKV, sATT, 0.03125f, 1);
    }
    // 3) P = softmax(S) in place (zeros above diagonal)
    softmax_causal_kernel<<<4 * 2048, 256>>>(att);

    // 4) y = P v        per batch, causal K-limit
    {
        dim3 grid(1024 / BN, 2048 / BM, 4);
        gemm_nn_kernel<<<grid, 256>>>(att, qkv + 2048, out,
                                      2048, 1024, 2048, 2048, 3072, 1024,
                                      sATT, sQKV, sOUT, 1.0f, 1);
    }
}

// round 3
// speedup vs baseline: 2.2659x; 2.2659x over previous
#include <cuda_runtime.h>
#include <cuda_bf16.h>
#include <cstdint>
#include <math.h>

// ---------------------------------------------------------------------------
// SingleHeadAttention B=4, T=2048, C=1024 fp32 — bf16-split mma.sync GEMMs
// (tcgen05 unavailable: harness PTX targets sm_100 baseline, not sm_100a)
//   qkv = x @ w^T        (NT, M=8192 N=3072 K=1024)
//   S   = q k^T / 32     (NT per batch, causal tile-skip)
//   P   = softmax(S)     -> bf16 hi/lo directly
//   y   = P @ (V^T)^T    (NT per batch, V pre-transposed, causal K-limit)
// Each GEMM: C = Ah*Bh^T + Ah*Bl^T + Al*Bh^T accumulated in fp32.
// ---------------------------------------------------------------------------

// ------------------------------ scratch (no allocs allowed) ----------------
__device__ float g_qkv[(size_t)8192 * 3072];
__device__ float g_att[(size_t)4 * 2048 * 2048];
__device__ __nv_bfloat16 g_xh[(size_t)8192 * 1024];
__device__ __nv_bfloat16 g_xl[(size_t)8192 * 1024];
__device__ __nv_bfloat16 g_wh[(size_t)3072 * 1024];
__device__ __nv_bfloat16 g_wl[(size_t)3072 * 1024];
__device__ __nv_bfloat16 g_qh[(size_t)4 * 2048 * 1024];
__device__ __nv_bfloat16 g_ql[(size_t)4 * 2048 * 1024];
__device__ __nv_bfloat16 g_kh[(size_t)4 * 2048 * 1024];
__device__ __nv_bfloat16 g_kl[(size_t)4 * 2048 * 1024];
__device__ __nv_bfloat16 g_vth[(size_t)4 * 1024 * 2048]; // V^T
__device__ __nv_bfloat16 g_vtl[(size_t)4 * 1024 * 2048];
__device__ __nv_bfloat16 g_ph[(size_t)4 * 2048 * 2048];
__device__ __nv_bfloat16 g_pl[(size_t)4 * 2048 * 2048];

// ------------------------------ mma-based NT GEMM --------------------------
// Tile: 128x128x32, 8 warps (4 m x 2 n), warp tile 32x64.
// smem rows padded: stride 40 bf16 (80B) -> conflict-free ldmatrix.
#define SA 40
#define TILE_B (128 * SA * 2)               // 10240 B per operand tile
#define STAGE_B (4 * TILE_B)                // Ah, Al, Bh, Bl
#define GEMM_SMEM (2 * STAGE_B)             // 81920 B

__device__ __forceinline__ uint32_t smem_u32(const void* p) {
    uint32_t a;
    asm("{ .reg .u64 t; cvta.to.shared.u64 t, %1; cvt.u32.u64 %0, t; }" : "=r"(a) : "l"(p));
    return a;
}
__device__ __forceinline__ void cp16(uint32_t dst, const void* src) {
    asm volatile("cp.async.cg.shared.global [%0], [%1], 16;" :: "r"(dst), "l"(src));
}
__device__ __forceinline__ void ldmx4(uint32_t* r, uint32_t addr) {
    asm volatile("ldmatrix.sync.aligned.m8n8.x4.shared.b16 {%0,%1,%2,%3}, [%4];"
                 : "=r"(r[0]), "=r"(r[1]), "=r"(r[2]), "=r"(r[3]) : "r"(addr));
}
__device__ __forceinline__ void mma16816(float* c, const uint32_t* a, const uint32_t* b) {
    asm volatile(
        "mma.sync.aligned.m16n8k16.row.col.f32.bf16.bf16.f32 "
        "{%0,%1,%2,%3}, {%4,%5,%6,%7}, {%8,%9}, {%0,%1,%2,%3};"
        : "+f"(c[0]), "+f"(c[1]), "+f"(c[2]), "+f"(c[3])
        : "r"(a[0]), "r"(a[1]), "r"(a[2]), "r"(a[3]), "r"(b[0]), "r"(b[1]));
}

__global__ __launch_bounds__(256, 1)
void gemm3_kernel(const __nv_bfloat16* __restrict__ Ah, const __nv_bfloat16* __restrict__ Al,
                  const __nv_bfloat16* __restrict__ Bh, const __nv_bfloat16* __restrict__ Bl,
                  float* __restrict__ C,
                  int K, int lda, int ldb, int ldc,
                  long long sAo, long long sBo, long long sCo,
                  float alpha, int causal_skip, int causal_klim)
{
    const int m0 = blockIdx.y * 128;
    const int n0 = blockIdx.x * 128;
    if (causal_skip && n0 > m0 + 127) return;

    const int bz = blockIdx.z;
    Ah += (long long)bz * sAo;  Al += (long long)bz * sAo;
    Bh += (long long)bz * sBo;  Bl += (long long)bz * sBo;
    C  += (long long)bz * sCo;

    int Keff = K;
    if (causal_klim) { int lim = m0 + 128; Keff = (lim < K) ? lim : K; }
    const int NC = Keff / 32;

    extern __shared__ char smem[];
    const uint32_t sb = smem_u32(smem);
    const int tid = threadIdx.x;
    const int wid = tid >> 5;
    const int lane = tid & 31;

    // ---- async stage loader: 4 tiles of [128 rows x 32 bf16] ----
    auto load_stage = [&](int s, int k0) {
        const uint32_t base = sb + s * STAGE_B;
#pragma unroll
        for (int it = 0; it < 2; ++it) {
            const int id  = tid + it * 256;     // 0..511
            const int row = id >> 2;
            const int c16 = id & 3;             // 16B chunk (8 bf16)
            const uint32_t so = (uint32_t)(row * SA + c16 * 8) * 2;
            const long long ga = (long long)(m0 + row) * lda + k0 + c16 * 8;
            const long long gb = (long long)(n0 + row) * ldb + k0 + c16 * 8;
            cp16(base + so,              Ah + ga);
            cp16(base + TILE_B + so,     Al + ga);
            cp16(base + 2 * TILE_B + so, Bh + gb);
            cp16(base + 3 * TILE_B + so, Bl + gb);
        }
        asm volatile("cp.async.commit_group;" ::: "memory");
    };

    float acc[2][8][4];
#pragma unroll
    for (int i = 0; i < 2; ++i)
#pragma unroll
        for (int j = 0; j < 8; ++j)
#pragma unroll
            for (int q = 0; q < 4; ++q) acc[i][j][q] = 0.f;

    const int wm = (wid & 3) * 32;      // warp m offset
    const int wn = (wid >> 2) * 64;     // warp n offset
    const int gr = lane >> 3;           // ldmatrix matrix id
    const int rr = lane & 7;            // row within matrix

    load_stage(0, 0);

    for (int c = 0; c < NC; ++c) {
        if (c + 1 < NC) {
            load_stage((c + 1) & 1, (c + 1) * 32);
            asm volatile("cp.async.wait_group 1;" ::: "memory");
        } else {
            asm volatile("cp.async.wait_group 0;" ::: "memory");
        }
        __syncthreads();

        const uint32_t st = sb + (c & 1) * STAGE_B;
#pragma unroll
        for (int kk = 0; kk < 32; kk += 16) {
            uint32_t ah[2][4], al[2][4], bf[8][2];
            // A frags: mats (m 0-7,k0),(m 8-15,k0),(m 0-7,k8),(m 8-15,k8)
#pragma unroll
            for (int mi = 0; mi < 2; ++mi) {
                const int arow = wm + mi * 16 + (gr & 1) * 8 + rr;
                const int acol = kk + (gr >> 1) * 8;
                const uint32_t off = (uint32_t)(arow * SA + acol) * 2;
                ldmx4(ah[mi], st + off);
                ldmx4(al[mi], st + TILE_B + off);
            }
            // B frags (Bh): mats (n0..7,k0),(n0..7,k8),(n8..15,k0),(n8..15,k8)
#pragma unroll
            for (int nt = 0; nt < 4; ++nt) {
                const int brow = wn + nt * 16 + (gr >> 1) * 8 + rr;
                const int bcol = kk + (gr & 1) * 8;
                uint32_t r[4];
                ldmx4(r, st + 2 * TILE_B + (uint32_t)(brow * SA + bcol) * 2);
                bf[nt * 2 + 0][0] = r[0]; bf[nt * 2 + 0][1] = r[1];
                bf[nt * 2 + 1][0] = r[2]; bf[nt * 2 + 1][1] = r[3];
            }
#pragma unroll
            for (int mi = 0; mi < 2; ++mi)
#pragma unroll
                for (int nj = 0; nj < 8; ++nj) {
                    mma16816(acc[mi][nj], ah[mi], bf[nj]);   // Ah*Bh
                    mma16816(acc[mi][nj], al[mi], bf[nj]);   // Al*Bh
                }
            // reload B <- Bl
#pragma unroll
            for (int nt = 0; nt < 4; ++nt) {
                const int brow = wn + nt * 16 + (gr >> 1) * 8 + rr;
                const int bcol = kk + (gr & 1) * 8;
                uint32_t r[4];
                ldmx4(r, st + 3 * TILE_B + (uint32_t)(brow * SA + bcol) * 2);
                bf[nt * 2 + 0][0] = r[0]; bf[nt * 2 + 0][1] = r[1];
                bf[nt * 2 + 1][0] = r[2]; bf[nt * 2 + 1][1] = r[3];
            }
#pragma unroll
            for (int mi = 0; mi < 2; ++mi)
#pragma unroll
                for (int nj = 0; nj < 8; ++nj)
                    mma16816(acc[mi][nj], ah[mi], bf[nj]);   // Ah*Bl
        }
        __syncthreads();
    }

    // ---- epilogue ----
#pragma unroll
    for (int mi = 0; mi < 2; ++mi)
#pragma unroll
        for (int nj = 0; nj < 8; ++nj) {
            const int row = m0 + wm + mi * 16 + (lane >> 2);
            const int col = n0 + wn + nj * 8 + (lane & 3) * 2;
            float2 v0 = make_float2(alpha * acc[mi][nj][0], alpha * acc[mi][nj][1]);
            float2 v1 = make_float2(alpha * acc[mi][nj][2], alpha * acc[mi][nj][3]);
            *(float2*)(C + (long long)row * ldc + col)       = v0;
            *(float2*)(C + (long long)(row + 8) * ldc + col) = v1;
        }
}

// ------------------------------ fp32 -> bf16 hi/lo splits ------------------
__global__ void split2_kernel(const float* __restrict__ src,
                              __nv_bfloat16* __restrict__ h, __nv_bfloat16* __restrict__ l,
                              long long n4)
{
    long long i = (long long)blockIdx.x * blockDim.x + threadIdx.x;
    if (i >= n4) return;
    float4 v = *(const float4*)(src + i * 4);
    __nv_bfloat16 hv[4], lv[4];
#pragma unroll
    for (int q = 0; q < 4; ++q) {
        float f = (&v.x)[q];
        hv[q] = __float2bfloat16(f);
        lv[q] = __float2bfloat16(f - __bfloat162float(hv[q]));
    }
    *(uint2*)(h + i * 4) = *(uint2*)hv;
    *(uint2*)(l + i * 4) = *(uint2*)lv;
}

__global__ void split_qk_kernel(const float* __restrict__ qkv,
                                __nv_bfloat16* __restrict__ qh, __nv_bfloat16* __restrict__ ql,
                                __nv_bfloat16* __restrict__ kh, __nv_bfloat16* __restrict__ kl)
{
    long long i = (long long)blockIdx.x * blockDim.x + threadIdx.x;
    const long long row = i >> 8;
    const int c4 = (int)(i & 255);
    const float* src = qkv + row * 3072 + c4 * 4;
    const long long dst = row * 1024 + c4 * 4;
#pragma unroll
    for (int part = 0; part < 2; ++part) {
        float4 v = *(const float4*)(src + part * 1024);
        __nv_bfloat16 hv[4], lv[4];
#pragma unroll
        for (int q = 0; q < 4; ++q) {
            float f = (&v.x)[q];
            hv[q] = __float2bfloat16(f);
            lv[q] = __float2bfloat16(f - __bfloat162float(hv[q]));
        }
        if (part == 0) { *(uint2*)(qh + dst) = *(uint2*)hv; *(uint2*)(ql + dst) = *(uint2*)lv; }
        else           { *(uint2*)(kh + dst) = *(uint2*)hv; *(uint2*)(kl + dst) = *(uint2*)lv; }
    }
}

__global__ void vtrans_kernel(const float* __restrict__ qkv,
                              __nv_bfloat16* __restrict__ vth, __nv_bfloat16* __restrict__ vtl)
{
    __shared__ float tile[32][33];
    const int s0 = blockIdx.x * 32, c0 = blockIdx.y * 32, b = blockIdx.z;
    const int tx = threadIdx.x, ty = threadIdx.y;   // (32, 8)
#pragma unroll
    for (int j = 0; j < 4; ++j) {
        const int s = s0 + ty + j * 8;
        tile[ty + j * 8][tx] = qkv[(long long)(b * 2048 + s) * 3072 + 2048 + c0 + tx];
    }
    __syncthreads();
#pragma unroll
    for (int j = 0; j < 4; ++j) {
        const int c = c0 + ty + j * 8;
        const float v = tile[tx][ty + j * 8];
        const long long o = ((long long)b * 1024 + c) * 2048 + s0 + tx;
        __nv_bfloat16 h = __float2bfloat16(v);
        vth[o] = h;
        vtl[o] = __float2bfloat16(v - __bfloat162float(h));
    }
}

// ------------------------------ causal softmax -> bf16 hi/lo ---------------
__global__ void softmax_causal_kernel(float* __restrict__ att,
                                      __nv_bfloat16* __restrict__ ph,
                                      __nv_bfloat16* __restrict__ pl)
{
    const int row = blockIdx.x;
    const int b = row >> 11, t = row & 2047;
    float* p = att + ((long long)b * 2048 + t) * 2048;
    __nv_bfloat16* hrow = ph + ((long long)b * 2048 + t) * 2048;
    __nv_bfloat16* lrow = pl + ((long long)b * 2048 + t) * 2048;
    const int n = t + 1;
    const int tid = threadIdx.x;
    __shared__ float sbuf[8];

    float m = -3.4e38f;
    for (int i = tid; i < n; i += 256) m = fmaxf(m, p[i]);
#pragma unroll
    for (int o = 16; o > 0; o >>= 1) m = fmaxf(m, __shfl_xor_sync(0xffffffffu, m, o));
    if ((tid & 31) == 0) sbuf[tid >> 5] = m;
    __syncthreads();
    if (tid < 8) {
        float v = sbuf[tid];
#pragma unroll
        for (int o = 4; o > 0; o >>= 1) v = fmaxf(v, __shfl_xor_sync(0xffu, v, o));
        if (tid == 0) sbuf[0] = v;
    }
    __syncthreads();
    m = sbuf[0];
    __syncthreads();

    float s = 0.f;
    for (int i = tid; i < n; i += 256) {
        float e = __expf(p[i] - m);
        s += e;
        p[i] = e;
    }
#pragma unroll
    for (int o = 16; o > 0; o >>= 1) s += __shfl_xor_sync(0xffffffffu, s, o);
    if ((tid & 31) == 0) sbuf[tid >> 5] = s;
    __syncthreads();
    if (tid < 8) {
        float v = sbuf[tid];
#pragma unroll
        for (int o = 4; o > 0; o >>= 1) v += __shfl_xor_sync(0xffu, v, o);
        if (tid == 0) sbuf[0] = v;
    }
    __syncthreads();
    const float inv = 1.f / sbuf[0];
    __syncthreads();

    for (int i = tid; i < 2048; i += 256) {
        if (i < n) {
            const float v = p[i] * inv;
            const __nv_bfloat16 h = __float2bfloat16(v);
            hrow[i] = h;
            lrow[i] = __float2bfloat16(v - __bfloat162float(h));
        } else {
            hrow[i] = __float2bfloat16(0.f);
            lrow[i] = __float2bfloat16(0.f);
        }
    }
}

// ---------------------------------------------------------------------------
extern "C" void kernel_launch(void* const* d_in, const int* in_sizes, int n_in,
                              void* d_out, int out_size)
{
    const float* x = (const float*)d_in[0];
    const float* w = (const float*)d_in[1];
    float* out = (float*)d_out;

    float *qkv, *att;
    __nv_bfloat16 *xh, *xl, *wh, *wl, *qh, *ql, *kh, *kl, *vth, *vtl, *phb, *plb;
    cudaGetSymbolAddress((void**)&qkv, g_qkv);
    cudaGetSymbolAddress((void**)&att, g_att);
    cudaGetSymbolAddress((void**)&xh, g_xh);   cudaGetSymbolAddress((void**)&xl, g_xl);
    cudaGetSymbolAddress((void**)&wh, g_wh);   cudaGetSymbolAddress((void**)&wl, g_wl);
    cudaGetSymbolAddress((void**)&qh, g_qh);   cudaGetSymbolAddress((void**)&ql, g_ql);
    cudaGetSymbolAddress((void**)&kh, g_kh);   cudaGetSymbolAddress((void**)&kl, g_kl);
    cudaGetSymbolAddress((void**)&vth, g_vth); cudaGetSymbolAddress((void**)&vtl, g_vtl);
    cudaGetSymbolAddress((void**)&phb, g_ph);  cudaGetSymbolAddress((void**)&plb, g_pl);

    cudaFuncSetAttribute(gemm3_kernel, cudaFuncAttributeMaxDynamicSharedMemorySize,
                         GEMM_SMEM);

    // 1) split inputs
    split2_kernel<<<(8192 * 1024 / 4 + 255) / 256, 256>>>(x, xh, xl, 8192LL * 1024 / 4);
    split2_kernel<<<(3072 * 1024 / 4 + 255) / 256, 256>>>(w, wh, wl, 3072LL * 1024 / 4);

    // 2) qkv = x @ w^T
    {
        dim3 grid(3072 / 128, 8192 / 128, 1);
        gemm3_kernel<<<grid, 256, GEMM_SMEM>>>(xh, xl, wh, wl, qkv,
                                               1024, 1024, 1024, 3072,
                                               0, 0, 0, 1.0f, 0, 0);
    }
    // 3) split q/k, transpose+split v
    split_qk_kernel<<<(4 * 2048 * 1024 / 4) / 256, 256>>>(qkv, qh, ql, kh, kl);
    {
        dim3 grid(2048 / 32, 1024 / 32, 4);
        vtrans_kernel<<<grid, dim3(32, 8)>>>(qkv, vth, vtl);
    }
    // 4) S = q k^T / 32  (causal tile skip)
    {
        dim3 grid(2048 / 128, 2048 / 128, 4);
        gemm3_kernel<<<grid, 256, GEMM_SMEM>>>(qh, ql, kh, kl, att,
                                               1024, 1024, 1024, 2048,
                                               2048LL * 1024, 2048LL * 1024, 2048LL * 2048,
                                               0.03125f, 1, 0);
    }
    // 5) P = softmax(S) -> bf16 hi/lo
    softmax_causal_kernel<<<4 * 2048, 256>>>(att, phb, plb);

    // 6) y = P @ V  (V^T K-major, causal K-limit)
    {
        dim3 grid(1024 / 128, 2048 / 128, 4);
        gemm3_kernel<<<grid, 256, GEMM_SMEM>>>(phb, plb, vth, vtl, out,
                                               2048, 2048, 2048, 1024,
                                               2048LL * 2048, 1024LL * 2048, 2048LL * 1024,
                                               1.0f, 0, 1);
    }
}

// round 4
// speedup vs baseline: 2.4098x; 1.0635x over previous
#include <cuda_runtime.h>
#include <cuda_bf16.h>
#include <cstdint>
#include <math.h>

// ---------------------------------------------------------------------------
// SingleHeadAttention B=4, T=2048, C=1024 fp32 — bf16-split mma.sync GEMMs
//   qkv = x @ w^T   (NT, fused epilogue -> qh/ql, kh/kl, v fp32)
//   S   = q k^T/32  (NT per batch, causal tile-skip)  -> att fp32
//   P   = softmax   -> bf16 hi/lo (register-resident exp, tile-bounded zeros)
//   y   = P @ (V^T)^T (NT per batch, causal K-limit)
// GEMM: C = Ah*Bh^T + Ah*Bl^T + Al*Bh^T, fp32 accum.
// Tile: 256x128 CTA, 8 warps (4m x 2n) of 64x64, k-chunk 32, 3-stage cp.async.
// ---------------------------------------------------------------------------

// ------------------------------ scratch ------------------------------------
__device__ float g_att[(size_t)4 * 2048 * 2048];
__device__ float g_vf[(size_t)4 * 2048 * 1024];          // v fp32 compact
__device__ __nv_bfloat16 g_xh[(size_t)8192 * 1024];
__device__ __nv_bfloat16 g_xl[(size_t)8192 * 1024];
__device__ __nv_bfloat16 g_wh[(size_t)3072 * 1024];
__device__ __nv_bfloat16 g_wl[(size_t)3072 * 1024];
__device__ __nv_bfloat16 g_qh[(size_t)4 * 2048 * 1024];
__device__ __nv_bfloat16 g_ql[(size_t)4 * 2048 * 1024];
__device__ __nv_bfloat16 g_kh[(size_t)4 * 2048 * 1024];
__device__ __nv_bfloat16 g_kl[(size_t)4 * 2048 * 1024];
__device__ __nv_bfloat16 g_vth[(size_t)4 * 1024 * 2048]; // V^T
__device__ __nv_bfloat16 g_vtl[(size_t)4 * 1024 * 2048];
__device__ __nv_bfloat16 g_ph[(size_t)4 * 2048 * 2048];
__device__ __nv_bfloat16 g_pl[(size_t)4 * 2048 * 2048];

// ------------------------------ helpers ------------------------------------
#define SA 40                                // padded smem row stride (bf16)
#define ATILE_B (256 * SA * 2)               // 20480
#define BTILE_B (128 * SA * 2)               // 10240
#define STAGE_B (2 * ATILE_B + 2 * BTILE_B)  // 61440
#define GEMM_SMEM (3 * STAGE_B)              // 184320

__device__ __forceinline__ uint32_t smem_u32(const void* p) {
    uint32_t a;
    asm("{ .reg .u64 t; cvta.to.shared.u64 t, %1; cvt.u32.u64 %0, t; }" : "=r"(a) : "l"(p));
    return a;
}
__device__ __forceinline__ void cp16(uint32_t dst, const void* src) {
    asm volatile("cp.async.cg.shared.global [%0], [%1], 16;" :: "r"(dst), "l"(src));
}
__device__ __forceinline__ void ldmx4(uint32_t* r, uint32_t addr) {
    asm volatile("ldmatrix.sync.aligned.m8n8.x4.shared.b16 {%0,%1,%2,%3}, [%4];"
                 : "=r"(r[0]), "=r"(r[1]), "=r"(r[2]), "=r"(r[3]) : "r"(addr));
}
__device__ __forceinline__ void mma16816(float* c, const uint32_t* a, const uint32_t* b) {
    asm volatile(
        "mma.sync.aligned.m16n8k16.row.col.f32.bf16.bf16.f32 "
        "{%0,%1,%2,%3}, {%4,%5,%6,%7}, {%8,%9}, {%0,%1,%2,%3};"
        : "+f"(c[0]), "+f"(c[1]), "+f"(c[2]), "+f"(c[3])
        : "r"(a[0]), "r"(a[1]), "r"(a[2]), "r"(a[3]), "r"(b[0]), "r"(b[1]));
}
__device__ __forceinline__ uint32_t pack2bf(float v0, float v1) {
    __nv_bfloat16 h0 = __float2bfloat16(v0), h1 = __float2bfloat16(v1);
    return ((uint32_t)*(uint16_t*)&h1 << 16) | *(uint16_t*)&h0;
}

// ------------------------------ GEMM ---------------------------------------
// mode 0: C = alpha * acc (fp32)
// mode 1: fused qkv split epilogue (n segment q/k -> bf16 hi/lo, v -> g_vf)
__global__ __launch_bounds__(256, 1)
void gemm3_kernel(const __nv_bfloat16* __restrict__ Ah, const __nv_bfloat16* __restrict__ Al,
                  const __nv_bfloat16* __restrict__ Bh, const __nv_bfloat16* __restrict__ Bl,
                  float* __restrict__ C,
                  int K, int lda, int ldb, int ldc,
                  long long sAo, long long sBo, long long sCo,
                  float alpha, int causal_skip, int causal_klim, int mode)
{
    const int m0 = blockIdx.y * 256;
    const int n0 = blockIdx.x * 128;
    if (causal_skip && n0 > m0 + 255) return;

    const int bz = blockIdx.z;
    Ah += (long long)bz * sAo;  Al += (long long)bz * sAo;
    Bh += (long long)bz * sBo;  Bl += (long long)bz * sBo;
    C  += (long long)bz * sCo;

    int Keff = K;
    if (causal_klim) { int lim = m0 + 256; Keff = (lim < K) ? lim : K; }
    const int NC = Keff / 32;

    extern __shared__ char smem[];
    const uint32_t sb = smem_u32(smem);
    const int tid = threadIdx.x;
    const int wid = tid >> 5;
    const int lane = tid & 31;

    auto load_stage = [&](int s, int c) {
        const uint32_t base = sb + s * STAGE_B;
        const int k0 = c * 32;
#pragma unroll
        for (int it = 0; it < 4; ++it) {        // A: 256 rows x 4 chunks
            const int id  = tid + it * 256;     // 0..1023
            const int row = id >> 2;
            const int c16 = id & 3;
            const uint32_t so = (uint32_t)(row * SA + c16 * 8) * 2;
            const long long ga = (long long)(m0 + row) * lda + k0 + c16 * 8;
            cp16(base + so,           Ah + ga);
            cp16(base + ATILE_B + so, Al + ga);
        }
#pragma unroll
        for (int it = 0; it < 2; ++it) {        // B: 128 rows x 4 chunks
            const int id  = tid + it * 256;     // 0..511
            const int row = id >> 2;
            const int c16 = id & 3;
            const uint32_t so = (uint32_t)(row * SA + c16 * 8) * 2;
            const long long gb = (long long)(n0 + row) * ldb + k0 + c16 * 8;
            cp16(base + 2 * ATILE_B + so,           Bh + gb);
            cp16(base + 2 * ATILE_B + BTILE_B + so, Bl + gb);
        }
        asm volatile("cp.async.commit_group;" ::: "memory");
    };

    float acc[4][8][4];
#pragma unroll
    for (int i = 0; i < 4; ++i)
#pragma unroll
        for (int j = 0; j < 8; ++j)
#pragma unroll
            for (int q = 0; q < 4; ++q) acc[i][j][q] = 0.f;

    const int wm = (wid & 3) * 64;
    const int wn = (wid >> 2) * 64;
    const int gr = lane >> 3;
    const int rr = lane & 7;

    load_stage(0, 0);
    load_stage(1, 1);

    for (int c = 0; c < NC; ++c) {
        if (c + 2 < NC) {
            asm volatile("cp.async.wait_group 1;" ::: "memory");
            __syncthreads();
            load_stage((c + 2) % 3, c + 2);
        } else {
            asm volatile("cp.async.wait_group 0;" ::: "memory");
            __syncthreads();
        }

        const uint32_t st = sb + (c % 3) * STAGE_B;
#pragma unroll
        for (int kk = 0; kk < 32; kk += 16) {
            uint32_t ah[4][4], al[4][4], bh[8][2], bl[8][2];
#pragma unroll
            for (int mi = 0; mi < 4; ++mi) {
                const int arow = wm + mi * 16 + (gr & 1) * 8 + rr;
                const int acol = kk + (gr >> 1) * 8;
                const uint32_t off = (uint32_t)(arow * SA + acol) * 2;
                ldmx4(ah[mi], st + off);
                ldmx4(al[mi], st + ATILE_B + off);
            }
#pragma unroll
            for (int nt = 0; nt < 4; ++nt) {
                const int brow = wn + nt * 16 + (gr >> 1) * 8 + rr;
                const int bcol = kk + (gr & 1) * 8;
                const uint32_t off = (uint32_t)(brow * SA + bcol) * 2;
                uint32_t r[4];
                ldmx4(r, st + 2 * ATILE_B + off);
                bh[nt * 2 + 0][0] = r[0]; bh[nt * 2 + 0][1] = r[1];
                bh[nt * 2 + 1][0] = r[2]; bh[nt * 2 + 1][1] = r[3];
                ldmx4(r, st + 2 * ATILE_B + BTILE_B + off);
                bl[nt * 2 + 0][0] = r[0]; bl[nt * 2 + 0][1] = r[1];
                bl[nt * 2 + 1][0] = r[2]; bl[nt * 2 + 1][1] = r[3];
            }
#pragma unroll
            for (int mi = 0; mi < 4; ++mi)
#pragma unroll
                for (int nj = 0; nj < 8; ++nj) {
                    mma16816(acc[mi][nj], ah[mi], bh[nj]);
                    mma16816(acc[mi][nj], al[mi], bh[nj]);
                    mma16816(acc[mi][nj], ah[mi], bl[nj]);
                }
        }
        __syncthreads();
    }

    // ---- epilogue ----
    if (mode == 0) {
#pragma unroll
        for (int mi = 0; mi < 4; ++mi)
#pragma unroll
            for (int nj = 0; nj < 8; ++nj) {
                const int row = m0 + wm + mi * 16 + (lane >> 2);
                const int col = n0 + wn + nj * 8 + (lane & 3) * 2;
                float2 v0 = make_float2(alpha * acc[mi][nj][0], alpha * acc[mi][nj][1]);
                float2 v1 = make_float2(alpha * acc[mi][nj][2], alpha * acc[mi][nj][3]);
                *(float2*)(C + (long long)row * ldc + col)       = v0;
                *(float2*)(C + (long long)(row + 8) * ldc + col) = v1;
            }
    } else {
        // fused qkv split: whole CTA lies in one of q / k / v (128 | 1024)
        const int seg = n0 >> 10;                       // 0=q 1=k 2=v
        __nv_bfloat16* dh = (seg == 0) ? g_qh : g_kh;
        __nv_bfloat16* dl = (seg == 0) ? g_ql : g_kl;
#pragma unroll
        for (int mi = 0; mi < 4; ++mi)
#pragma unroll
            for (int nj = 0; nj < 8; ++nj) {
                const int row = m0 + wm + mi * 16 + (lane >> 2);
                const int cc  = (n0 & 1023) + wn + nj * 8 + (lane & 3) * 2;
                const float v00 = acc[mi][nj][0], v01 = acc[mi][nj][1];
                const float v10 = acc[mi][nj][2], v11 = acc[mi][nj][3];
                if (seg == 2) {
                    *(float2*)(g_vf + (long long)row * 1024 + cc)       = make_float2(v00, v01);
                    *(float2*)(g_vf + (long long)(row + 8) * 1024 + cc) = make_float2(v10, v11);
                } else {
                    const long long o0 = (long long)row * 1024 + cc;
                    const long long o1 = (long long)(row + 8) * 1024 + cc;
                    __nv_bfloat16 h00 = __float2bfloat16(v00), h01 = __float2bfloat16(v01);
                    __nv_bfloat16 h10 = __float2bfloat16(v10), h11 = __float2bfloat16(v11);
                    *(uint32_t*)(dh + o0) = ((uint32_t)*(uint16_t*)&h01 << 16) | *(uint16_t*)&h00;
                    *(uint32_t*)(dh + o1) = ((uint32_t)*(uint16_t*)&h11 << 16) | *(uint16_t*)&h10;
                    *(uint32_t*)(dl + o0) = pack2bf(v00 - __bfloat162float(h00),
                                                    v01 - __bfloat162float(h01));
                    *(uint32_t*)(dl + o1) = pack2bf(v10 - __bfloat162float(h10),
                                                    v11 - __bfloat162float(h11));
                }
            }
    }
}

// ------------------------------ input splits -------------------------------
__global__ void split2_kernel(const float* __restrict__ src,
                              __nv_bfloat16* __restrict__ h, __nv_bfloat16* __restrict__ l,
                              long long n4)
{
    long long i = (long long)blockIdx.x * blockDim.x + threadIdx.x;
    if (i >= n4) return;
    float4 v = *(const float4*)(src + i * 4);
    __nv_bfloat16 hv[4], lv[4];
#pragma unroll
    for (int q = 0; q < 4; ++q) {
        float f = (&v.x)[q];
        hv[q] = __float2bfloat16(f);
        lv[q] = __float2bfloat16(f - __bfloat162float(hv[q]));
    }
    *(uint2*)(h + i * 4) = *(uint2*)hv;
    *(uint2*)(l + i * 4) = *(uint2*)lv;
}

// V transpose + split: vT[b][c][s] = vf[b*2048+s][c]
__global__ void vtrans_kernel(const float* __restrict__ vf,
                              __nv_bfloat16* __restrict__ vth, __nv_bfloat16* __restrict__ vtl)
{
    __shared__ float tile[32][33];
    const int s0 = blockIdx.x * 32, c0 = blockIdx.y * 32, b = blockIdx.z;
    const int tx = threadIdx.x, ty = threadIdx.y;   // (32, 8)
#pragma unroll
    for (int j = 0; j < 4; ++j) {
        const int s = s0 + ty + j * 8;
        tile[ty + j * 8][tx] = vf[(long long)(b * 2048 + s) * 1024 + c0 + tx];
    }
    __syncthreads();
#pragma unroll
    for (int j = 0; j < 4; ++j) {
        const int c = c0 + ty + j * 8;
        const float v = tile[tx][ty + j * 8];
        const long long o = ((long long)b * 1024 + c) * 2048 + s0 + tx;
        __nv_bfloat16 h = __float2bfloat16(v);
        vth[o] = h;
        vtl[o] = __float2bfloat16(v - __bfloat162float(h));
    }
}

// --------------------- causal softmax -> bf16 hi/lo ------------------------
// exp kept in registers (8 cols/thread); zero-fill only to the 256 tile bound.
__global__ void softmax_causal_kernel(const float* __restrict__ att,
                                      __nv_bfloat16* __restrict__ ph,
                                      __nv_bfloat16* __restrict__ pl)
{
    const int row = blockIdx.x;
    const int b = row >> 11, t = row & 2047;
    const float* p = att + ((long long)b * 2048 + t) * 2048;
    __nv_bfloat16* hrow = ph + ((long long)b * 2048 + t) * 2048;
    __nv_bfloat16* lrow = pl + ((long long)b * 2048 + t) * 2048;
    const int n = t + 1;
    const int zb = ((t >> 8) + 1) << 8;      // PV reads cols [0, zb)
    const int tid = threadIdx.x;
    __shared__ float sbuf[8];

    float e[8];
    float m = -3.4e38f;
#pragma unroll
    for (int j = 0; j < 8; ++j) {
        const int i = tid + j * 256;
        e[j] = (i < n) ? p[i] : -3.4e38f;
        m = fmaxf(m, e[j]);
    }
#pragma unroll
    for (int o = 16; o > 0; o >>= 1) m = fmaxf(m, __shfl_xor_sync(0xffffffffu, m, o));
    if ((tid & 31) == 0) sbuf[tid >> 5] = m;
    __syncthreads();
    if (tid < 8) {
        float v = sbuf[tid];
#pragma unroll
        for (int o = 4; o > 0; o >>= 1) v = fmaxf(v, __shfl_xor_sync(0xffu, v, o));
        if (tid == 0) sbuf[0] = v;
    }
    __syncthreads();
    m = sbuf[0];
    __syncthreads();

    float s = 0.f;
#pragma unroll
    for (int j = 0; j < 8; ++j) {
        const int i = tid + j * 256;
        e[j] = (i < n) ? __expf(e[j] - m) : 0.f;
        s += e[j];
    }
#pragma unroll
    for (int o = 16; o > 0; o >>= 1) s += __shfl_xor_sync(0xffffffffu, s, o);
    if ((tid & 31) == 0) sbuf[tid >> 5] = s;
    __syncthreads();
    if (tid < 8) {
        float v = sbuf[tid];
#pragma unroll
        for (int o = 4; o > 0; o >>= 1) v += __shfl_xor_sync(0xffu, v, o);
        if (tid == 0) sbuf[0] = v;
    }
    __syncthreads();
    const float inv = 1.f / sbuf[0];

#pragma unroll
    for (int j = 0; j < 8; ++j) {
        const int i = tid + j * 256;
        if (i >= zb) break;
        const float v = e[j] * inv;
        const __nv_bfloat16 h = __float2bfloat16(v);
        hrow[i] = h;
        lrow[i] = __float2bfloat16(v - __bfloat162float(h));
    }
}

// ---------------------------------------------------------------------------
extern "C" void kernel_launch(void* const* d_in, const int* in_sizes, int n_in,
                              void* d_out, int out_size)
{
    const float* x = (const float*)d_in[0];
    const float* w = (const float*)d_in[1];
    float* out = (float*)d_out;

    float *att, *vf;
    __nv_bfloat16 *xh, *xl, *wh, *wl, *qh, *ql, *kh, *kl, *vth, *vtl, *phb, *plb;
    cudaGetSymbolAddress((void**)&att, g_att);
    cudaGetSymbolAddress((void**)&vf, g_vf);
    cudaGetSymbolAddress((void**)&xh, g_xh);   cudaGetSymbolAddress((void**)&xl, g_xl);
    cudaGetSymbolAddress((void**)&wh, g_wh);   cudaGetSymbolAddress((void**)&wl, g_wl);
    cudaGetSymbolAddress((void**)&qh, g_qh);   cudaGetSymbolAddress((void**)&ql, g_ql);
    cudaGetSymbolAddress((void**)&kh, g_kh);   cudaGetSymbolAddress((void**)&kl, g_kl);
    cudaGetSymbolAddress((void**)&vth, g_vth); cudaGetSymbolAddress((void**)&vtl, g_vtl);
    cudaGetSymbolAddress((void**)&phb, g_ph);  cudaGetSymbolAddress((void**)&plb, g_pl);

    cudaFuncSetAttribute(gemm3_kernel, cudaFuncAttributeMaxDynamicSharedMemorySize,
                         GEMM_SMEM);

    // 1) split inputs
    split2_kernel<<<(8192 * 1024 / 4 + 255) / 256, 256>>>(x, xh, xl, 8192LL * 1024 / 4);
    split2_kernel<<<(3072 * 1024 / 4 + 255) / 256, 256>>>(w, wh, wl, 3072LL * 1024 / 4);

    // 2) qkv = x @ w^T  (fused split epilogue)
    {
        dim3 grid(3072 / 128, 8192 / 256, 1);
        gemm3_kernel<<<grid, 256, GEMM_SMEM>>>(xh, xl, wh, wl, nullptr,
                                               1024, 1024, 1024, 0,
                                               0, 0, 0, 1.0f, 0, 0, 1);
    }
    // 3) transpose+split v
    {
        dim3 grid(2048 / 32, 1024 / 32, 4);
        vtrans_kernel<<<grid, dim3(32, 8)>>>(vf, vth, vtl);
    }
    // 4) S = q k^T / 32  (causal tile skip)
    {
        dim3 grid(2048 / 128, 2048 / 256, 4);
        gemm3_kernel<<<grid, 256, GEMM_SMEM>>>(qh, ql, kh, kl, att,
                                               1024, 1024, 1024, 2048,
                                               2048LL * 1024, 2048LL * 1024, 2048LL * 2048,
                                               0.03125f, 1, 0, 0);
    }
    // 5) P = softmax(S) -> bf16 hi/lo
    softmax_causal_kernel<<<4 * 2048, 256>>>(att, phb, plb);

    // 6) y = P @ V  (V^T K-major, causal K-limit)
    {
        dim3 grid(1024 / 128, 2048 / 256, 4);
        gemm3_kernel<<<grid, 256, GEMM_SMEM>>>(phb, plb, vth, vtl, out,
                                               2048, 2048, 2048, 1024,
                                               2048LL * 2048, 1024LL * 2048, 2048LL * 1024,
                                               1.0f, 0, 1, 0);
    }
}

// round 5
// speedup vs baseline: 2.5066x; 1.0401x over previous
#include <cuda_runtime.h>
#include <cuda_bf16.h>
#include <cstdint>
#include <math.h>

// ---------------------------------------------------------------------------
// SingleHeadAttention B=4, T=2048, C=1024 fp32 — bf16-split mma.sync GEMMs
//   qkv = x @ w^T   (NT, fused epilogue -> qh/ql, kh/kl, v fp32)
//   S   = q k^T/32  (NT per batch, causal tile-skip)  -> att fp32
//   P   = softmax   -> bf16 hi/lo (register-resident, 128-aligned zero bound)
//   y   = P @ (V^T)^T (NT per batch, causal K-limit)
// GEMM: C = Ah*Bh^T + Ah*Bl^T + Al*Bh^T, fp32 accum.
// Tile: 128x256 CTA, 512 thr, 16 warps (2m x 8n) of 64x32, k=32, 3-stage.
// ---------------------------------------------------------------------------

// ------------------------------ scratch ------------------------------------
__device__ float g_att[(size_t)4 * 2048 * 2048];
__device__ float g_vf[(size_t)4 * 2048 * 1024];
__device__ __nv_bfloat16 g_xh[(size_t)8192 * 1024];
__device__ __nv_bfloat16 g_xl[(size_t)8192 * 1024];
__device__ __nv_bfloat16 g_wh[(size_t)3072 * 1024];
__device__ __nv_bfloat16 g_wl[(size_t)3072 * 1024];
__device__ __nv_bfloat16 g_qh[(size_t)4 * 2048 * 1024];
__device__ __nv_bfloat16 g_ql[(size_t)4 * 2048 * 1024];
__device__ __nv_bfloat16 g_kh[(size_t)4 * 2048 * 1024];
__device__ __nv_bfloat16 g_kl[(size_t)4 * 2048 * 1024];
__device__ __nv_bfloat16 g_vth[(size_t)4 * 1024 * 2048];
__device__ __nv_bfloat16 g_vtl[(size_t)4 * 1024 * 2048];
__device__ __nv_bfloat16 g_ph[(size_t)4 * 2048 * 2048];
__device__ __nv_bfloat16 g_pl[(size_t)4 * 2048 * 2048];

// ------------------------------ helpers ------------------------------------
#define SA 40                                 // padded smem row stride (bf16)
#define ATILE_B (128 * SA * 2)                // 10240 (A: 128 m-rows x 32 k)
#define BTILE_B (256 * SA * 2)                // 20480 (B: 256 n-rows x 32 k)
#define STAGE_B (2 * ATILE_B + 2 * BTILE_B)   // 61440
#define GEMM_SMEM (3 * STAGE_B)               // 184320

__device__ __forceinline__ uint32_t smem_u32(const void* p) {
    uint32_t a;
    asm("{ .reg .u64 t; cvta.to.shared.u64 t, %1; cvt.u32.u64 %0, t; }" : "=r"(a) : "l"(p));
    return a;
}
__device__ __forceinline__ void cp16(uint32_t dst, const void* src) {
    asm volatile("cp.async.cg.shared.global [%0], [%1], 16;" :: "r"(dst), "l"(src));
}
__device__ __forceinline__ void ldmx4(uint32_t* r, uint32_t addr) {
    asm volatile("ldmatrix.sync.aligned.m8n8.x4.shared.b16 {%0,%1,%2,%3}, [%4];"
                 : "=r"(r[0]), "=r"(r[1]), "=r"(r[2]), "=r"(r[3]) : "r"(addr));
}
__device__ __forceinline__ void mma16816(float* c, const uint32_t* a, const uint32_t* b) {
    asm volatile(
        "mma.sync.aligned.m16n8k16.row.col.f32.bf16.bf16.f32 "
        "{%0,%1,%2,%3}, {%4,%5,%6,%7}, {%8,%9}, {%0,%1,%2,%3};"
        : "+f"(c[0]), "+f"(c[1]), "+f"(c[2]), "+f"(c[3])
        : "r"(a[0]), "r"(a[1]), "r"(a[2]), "r"(a[3]), "r"(b[0]), "r"(b[1]));
}
__device__ __forceinline__ uint32_t pack2bf(float v0, float v1) {
    __nv_bfloat16 h0 = __float2bfloat16(v0), h1 = __float2bfloat16(v1);
    return ((uint32_t)*(uint16_t*)&h1 << 16) | *(uint16_t*)&h0;
}

// ------------------------------ GEMM ---------------------------------------
// mode 0: C = alpha * acc (fp32);  mode 1: fused qkv split epilogue
__global__ __launch_bounds__(512, 1)
void gemm3_kernel(const __nv_bfloat16* __restrict__ Ah, const __nv_bfloat16* __restrict__ Al,
                  const __nv_bfloat16* __restrict__ Bh, const __nv_bfloat16* __restrict__ Bl,
                  float* __restrict__ C,
                  int K, int lda, int ldb, int ldc,
                  long long sAo, long long sBo, long long sCo,
                  float alpha, int causal_skip, int causal_klim, int mode)
{
    const int m0 = blockIdx.y * 128;
    const int n0 = blockIdx.x * 256;
    if (causal_skip && n0 > m0 + 127) return;

    const int bz = blockIdx.z;
    Ah += (long long)bz * sAo;  Al += (long long)bz * sAo;
    Bh += (long long)bz * sBo;  Bl += (long long)bz * sBo;
    C  += (long long)bz * sCo;

    int Keff = K;
    if (causal_klim) { int lim = m0 + 128; Keff = (lim < K) ? lim : K; }
    const int NC = Keff / 32;

    extern __shared__ char smem[];
    const uint32_t sb = smem_u32(smem);
    const int tid = threadIdx.x;
    const int wid = tid >> 5;
    const int lane = tid & 31;

    auto load_stage = [&](int s, int c) {
        const uint32_t base = sb + s * STAGE_B;
        const int k0 = c * 32;
        {   // A: 128 rows x 4 chunks = 512 ids
            const int row = tid >> 2;
            const int c16 = tid & 3;
            const uint32_t so = (uint32_t)(row * SA + c16 * 8) * 2;
            const long long ga = (long long)(m0 + row) * lda + k0 + c16 * 8;
            cp16(base + so,           Ah + ga);
            cp16(base + ATILE_B + so, Al + ga);
        }
#pragma unroll
        for (int it = 0; it < 2; ++it) {  // B: 256 rows x 4 chunks = 1024 ids
            const int id  = tid + it * 512;
            const int row = id >> 2;
            const int c16 = id & 3;
            const uint32_t so = (uint32_t)(row * SA + c16 * 8) * 2;
            const long long gb = (long long)(n0 + row) * ldb + k0 + c16 * 8;
            cp16(base + 2 * ATILE_B + so,           Bh + gb);
            cp16(base + 2 * ATILE_B + BTILE_B + so, Bl + gb);
        }
        asm volatile("cp.async.commit_group;" ::: "memory");
    };

    float acc[4][4][4];
#pragma unroll
    for (int i = 0; i < 4; ++i)
#pragma unroll
        for (int j = 0; j < 4; ++j)
#pragma unroll
            for (int q = 0; q < 4; ++q) acc[i][j][q] = 0.f;

    const int wm = (wid & 1) * 64;       // warp m offset (0/64)
    const int wn = (wid >> 1) * 32;      // warp n offset (0..224)
    const int gr = lane >> 3;
    const int rr = lane & 7;

    // per-warp ldmatrix base offsets (within a stage)
    const uint32_t a_off = (uint32_t)((wm + (gr & 1) * 8 + rr) * SA + (gr >> 1) * 8) * 2;
    const uint32_t b_off = (uint32_t)((wn + (gr >> 1) * 8 + rr) * SA + (gr & 1) * 8) * 2;

    load_stage(0, 0);
    load_stage(1, 1);

    for (int c = 0; c < NC; ++c) {
        if (c + 2 < NC) {
            asm volatile("cp.async.wait_group 1;" ::: "memory");
            __syncthreads();
            load_stage((c + 2) % 3, c + 2);
        } else {
            asm volatile("cp.async.wait_group 0;" ::: "memory");
            __syncthreads();
        }

        const uint32_t st = sb + (c % 3) * STAGE_B;
#pragma unroll
        for (int kk = 0; kk < 32; kk += 16) {
            uint32_t ah[4][4], al[4][4], bb[4][2];
            const uint32_t koff = (uint32_t)kk * 2;
#pragma unroll
            for (int mi = 0; mi < 4; ++mi) {
                const uint32_t off = a_off + koff + (uint32_t)(mi * 16 * SA) * 2;
                ldmx4(ah[mi], st + off);
                ldmx4(al[mi], st + ATILE_B + off);
            }
            // Bh
#pragma unroll
            for (int nt = 0; nt < 2; ++nt) {
                uint32_t r[4];
                ldmx4(r, st + 2 * ATILE_B + b_off + koff + (uint32_t)(nt * 16 * SA) * 2);
                bb[nt * 2 + 0][0] = r[0]; bb[nt * 2 + 0][1] = r[1];
                bb[nt * 2 + 1][0] = r[2]; bb[nt * 2 + 1][1] = r[3];
            }
#pragma unroll
            for (int mi = 0; mi < 4; ++mi)
#pragma unroll
                for (int nj = 0; nj < 4; ++nj) {
                    mma16816(acc[mi][nj], ah[mi], bb[nj]);
                    mma16816(acc[mi][nj], al[mi], bb[nj]);
                }
            // Bl over Bh
#pragma unroll
            for (int nt = 0; nt < 2; ++nt) {
                uint32_t r[4];
                ldmx4(r, st + 2 * ATILE_B + BTILE_B + b_off + koff +
                          (uint32_t)(nt * 16 * SA) * 2);
                bb[nt * 2 + 0][0] = r[0]; bb[nt * 2 + 0][1] = r[1];
                bb[nt * 2 + 1][0] = r[2]; bb[nt * 2 + 1][1] = r[3];
            }
#pragma unroll
            for (int mi = 0; mi < 4; ++mi)
#pragma unroll
                for (int nj = 0; nj < 4; ++nj)
                    mma16816(acc[mi][nj], ah[mi], bb[nj]);
        }
        __syncthreads();
    }

    // ---- epilogue ----
    if (mode == 0) {
#pragma unroll
        for (int mi = 0; mi < 4; ++mi)
#pragma unroll
            for (int nj = 0; nj < 4; ++nj) {
                const int row = m0 + wm + mi * 16 + (lane >> 2);
                const int col = n0 + wn + nj * 8 + (lane & 3) * 2;
                float2 v0 = make_float2(alpha * acc[mi][nj][0], alpha * acc[mi][nj][1]);
                float2 v1 = make_float2(alpha * acc[mi][nj][2], alpha * acc[mi][nj][3]);
                *(float2*)(C + (long long)row * ldc + col)       = v0;
                *(float2*)(C + (long long)(row + 8) * ldc + col) = v1;
            }
    } else {
        const int seg = n0 >> 10;                      // 0=q 1=k 2=v
        __nv_bfloat16* dh = (seg == 0) ? g_qh : g_kh;
        __nv_bfloat16* dl = (seg == 0) ? g_ql : g_kl;
#pragma unroll
        for (int mi = 0; mi < 4; ++mi)
#pragma unroll
            for (int nj = 0; nj < 4; ++nj) {
                const int row = m0 + wm + mi * 16 + (lane >> 2);
                const int cc  = (n0 & 1023) + wn + nj * 8 + (lane & 3) * 2;
                const float v00 = acc[mi][nj][0], v01 = acc[mi][nj][1];
                const float v10 = acc[mi][nj][2], v11 = acc[mi][nj][3];
                if (seg == 2) {
                    *(float2*)(g_vf + (long long)row * 1024 + cc)       = make_float2(v00, v01);
                    *(float2*)(g_vf + (long long)(row + 8) * 1024 + cc) = make_float2(v10, v11);
                } else {
                    const long long o0 = (long long)row * 1024 + cc;
                    const long long o1 = (long long)(row + 8) * 1024 + cc;
                    __nv_bfloat16 h00 = __float2bfloat16(v00), h01 = __float2bfloat16(v01);
                    __nv_bfloat16 h10 = __float2bfloat16(v10), h11 = __float2bfloat16(v11);
                    *(uint32_t*)(dh + o0) = ((uint32_t)*(uint16_t*)&h01 << 16) | *(uint16_t*)&h00;
                    *(uint32_t*)(dh + o1) = ((uint32_t)*(uint16_t*)&h11 << 16) | *(uint16_t*)&h10;
                    *(uint32_t*)(dl + o0) = pack2bf(v00 - __bfloat162float(h00),
                                                    v01 - __bfloat162float(h01));
                    *(uint32_t*)(dl + o1) = pack2bf(v10 - __bfloat162float(h10),
                                                    v11 - __bfloat162float(h11));
                }
            }
    }
}

// ------------------------------ input splits -------------------------------
__global__ void split2_kernel(const float* __restrict__ src,
                              __nv_bfloat16* __restrict__ h, __nv_bfloat16* __restrict__ l,
                              long long n4)
{
    long long i = (long long)blockIdx.x * blockDim.x + threadIdx.x;
    if (i >= n4) return;
    float4 v = *(const float4*)(src + i * 4);
    __nv_bfloat16 hv[4], lv[4];
#pragma unroll
    for (int q = 0; q < 4; ++q) {
        float f = (&v.x)[q];
        hv[q] = __float2bfloat16(f);
        lv[q] = __float2bfloat16(f - __bfloat162float(hv[q]));
    }
    *(uint2*)(h + i * 4) = *(uint2*)hv;
    *(uint2*)(l + i * 4) = *(uint2*)lv;
}

__global__ void vtrans_kernel(const float* __restrict__ vf,
                              __nv_bfloat16* __restrict__ vth, __nv_bfloat16* __restrict__ vtl)
{
    __shared__ float tile[32][33];
    const int s0 = blockIdx.x * 32, c0 = blockIdx.y * 32, b = blockIdx.z;
    const int tx = threadIdx.x, ty = threadIdx.y;
#pragma unroll
    for (int j = 0; j < 4; ++j) {
        const int s = s0 + ty + j * 8;
        tile[ty + j * 8][tx] = vf[(long long)(b * 2048 + s) * 1024 + c0 + tx];
    }
    __syncthreads();
#pragma unroll
    for (int j = 0; j < 4; ++j) {
        const int c = c0 + ty + j * 8;
        const float v = tile[tx][ty + j * 8];
        const long long o = ((long long)b * 1024 + c) * 2048 + s0 + tx;
        __nv_bfloat16 h = __float2bfloat16(v);
        vth[o] = h;
        vtl[o] = __float2bfloat16(v - __bfloat162float(h));
    }
}

// --------------------- causal softmax -> bf16 hi/lo ------------------------
__global__ void softmax_causal_kernel(const float* __restrict__ att,
                                      __nv_bfloat16* __restrict__ ph,
                                      __nv_bfloat16* __restrict__ pl)
{
    const int row = blockIdx.x;
    const int b = row >> 11, t = row & 2047;
    const float* p = att + ((long long)b * 2048 + t) * 2048;
    __nv_bfloat16* hrow = ph + ((long long)b * 2048 + t) * 2048;
    __nv_bfloat16* lrow = pl + ((long long)b * 2048 + t) * 2048;
    const int n = t + 1;
    const int zb = ((t >> 7) + 1) << 7;    // PV K-limit is 128-aligned now
    const int tid = threadIdx.x;
    __shared__ float sbuf[8];

    float e[8];
    float m = -3.4e38f;
#pragma unroll
    for (int j = 0; j < 8; ++j) {
        const int i = tid + j * 256;
        e[j] = (i < n) ? p[i] : -3.4e38f;
        m = fmaxf(m, e[j]);
    }
#pragma unroll
    for (int o = 16; o > 0; o >>= 1) m = fmaxf(m, __shfl_xor_sync(0xffffffffu, m, o));
    if ((tid & 31) == 0) sbuf[tid >> 5] = m;
    __syncthreads();
    if (tid < 8) {
        float v = sbuf[tid];
#pragma unroll
        for (int o = 4; o > 0; o >>= 1) v = fmaxf(v, __shfl_xor_sync(0xffu, v, o));
        if (tid == 0) sbuf[0] = v;
    }
    __syncthreads();
    m = sbuf[0];
    __syncthreads();

    float s = 0.f;
#pragma unroll
    for (int j = 0; j < 8; ++j) {
        const int i = tid + j * 256;
        e[j] = (i < n) ? __expf(e[j] - m) : 0.f;
        s += e[j];
    }
#pragma unroll
    for (int o = 16; o > 0; o >>= 1) s += __shfl_xor_sync(0xffffffffu, s, o);
    if ((tid & 31) == 0) sbuf[tid >> 5] = s;
    __syncthreads();
    if (tid < 8) {
        float v = sbuf[tid];
#pragma unroll
        for (int o = 4; o > 0; o >>= 1) v += __shfl_xor_sync(0xffu, v, o);
        if (tid == 0) sbuf[0] = v;
    }
    __syncthreads();
    const float inv = 1.f / sbuf[0];

#pragma unroll
    for (int j = 0; j < 8; ++j) {
        const int i = tid + j * 256;
        if (i >= zb) break;
        const float v = e[j] * inv;
        const __nv_bfloat16 h = __float2bfloat16(v);
        hrow[i] = h;
        lrow[i] = __float2bfloat16(v - __bfloat162float(h));
    }
}

// ---------------------------------------------------------------------------
extern "C" void kernel_launch(void* const* d_in, const int* in_sizes, int n_in,
                              void* d_out, int out_size)
{
    const float* x = (const float*)d_in[0];
    const float* w = (const float*)d_in[1];
    float* out = (float*)d_out;

    float *att, *vf;
    __nv_bfloat16 *xh, *xl, *wh, *wl, *qh, *ql, *kh, *kl, *vth, *vtl, *phb, *plb;
    cudaGetSymbolAddress((void**)&att, g_att);
    cudaGetSymbolAddress((void**)&vf, g_vf);
    cudaGetSymbolAddress((void**)&xh, g_xh);   cudaGetSymbolAddress((void**)&xl, g_xl);
    cudaGetSymbolAddress((void**)&wh, g_wh);   cudaGetSymbolAddress((void**)&wl, g_wl);
    cudaGetSymbolAddress((void**)&qh, g_qh);   cudaGetSymbolAddress((void**)&ql, g_ql);
    cudaGetSymbolAddress((void**)&kh, g_kh);   cudaGetSymbolAddress((void**)&kl, g_kl);
    cudaGetSymbolAddress((void**)&vth, g_vth); cudaGetSymbolAddress((void**)&vtl, g_vtl);
    cudaGetSymbolAddress((void**)&phb, g_ph);  cudaGetSymbolAddress((void**)&plb, g_pl);

    cudaFuncSetAttribute(gemm3_kernel, cudaFuncAttributeMaxDynamicSharedMemorySize,
                         GEMM_SMEM);

    // 1) split inputs
    split2_kernel<<<(8192 * 1024 / 4 + 255) / 256, 256>>>(x, xh, xl, 8192LL * 1024 / 4);
    split2_kernel<<<(3072 * 1024 / 4 + 255) / 256, 256>>>(w, wh, wl, 3072LL * 1024 / 4);

    // 2) qkv = x @ w^T  (fused split epilogue)
    {
        dim3 grid(3072 / 256, 8192 / 128, 1);
        gemm3_kernel<<<grid, 512, GEMM_SMEM>>>(xh, xl, wh, wl, nullptr,
                                               1024, 1024, 1024, 0,
                                               0, 0, 0, 1.0f, 0, 0, 1);
    }
    // 3) transpose+split v
    {
        dim3 grid(2048 / 32, 1024 / 32, 4);
        vtrans_kernel<<<grid, dim3(32, 8)>>>(vf, vth, vtl);
    }
    // 4) S = q k^T / 32  (causal tile skip)
    {
        dim3 grid(2048 / 256, 2048 / 128, 4);
        gemm3_kernel<<<grid, 512, GEMM_SMEM>>>(qh, ql, kh, kl, att,
                                               1024, 1024, 1024, 2048,
                                               2048LL * 1024, 2048LL * 1024, 2048LL * 2048,
                                               0.03125f, 1, 0, 0);
    }
    // 5) P = softmax(S) -> bf16 hi/lo
    softmax_causal_kernel<<<4 * 2048, 256>>>(att, phb, plb);

    // 6) y = P @ V  (V^T K-major, causal K-limit)
    {
        dim3 grid(1024 / 256, 2048 / 128, 4);
        gemm3_kernel<<<grid, 512, GEMM_SMEM>>>(phb, plb, vth, vtl, out,
                                               2048, 2048, 2048, 1024,
                                               2048LL * 2048, 1024LL * 2048, 2048LL * 1024,
                                               1.0f, 0, 1, 0);
    }
}